// round 10
// baseline (speedup 1.0000x reference)
#include <cuda_runtime.h>
#include <cuda_fp16.h>
#include <cstdint>

#define DM 1024
#define DN 4096
#define BB 2
#define TT 4096
#define MTOT 8192   // BB*TT

// ---------------- scratch (device globals) ----------------------------------
__device__ __half  g_xh[8388608];      // fp16 X [8192,1024]
__device__ __half  g_wh[16777216];     // fp16 W_cat interleaved [16384,1024]; row = ch*4+w
__device__ __half  g_wouth[4194304];   // fp16 W_out [1024,4096]
__device__ float2  g_du[33554432];     // {decay, update} [8192,4096]
__device__ float2  g_gh[33554432];     // {g, h}          [8192,4096]
__device__ __half  g_yh[33554432];     // fp16 y          [8192,4096]

// ---------------- helpers ----------------------------------------------------
__device__ __forceinline__ uint32_t smem_u32(const void* p) {
    uint32_t a;
    asm("{ .reg .u64 t; cvta.to.shared.u64 t, %1; cvt.u32.u64 %0, t; }" : "=r"(a) : "l"(p));
    return a;
}

#define CPA16(dst, src) asm volatile("cp.async.cg.shared.global [%0], [%1], 16;" :: "r"(dst), "l"(src) : "memory")
#define CPA_COMMIT()    asm volatile("cp.async.commit_group;" ::: "memory")
#define CPA_WAIT2()     asm volatile("cp.async.wait_group 2;" ::: "memory")

// m16n8k16 fp16 mma, fp32 accum
__device__ __forceinline__ void mma16(float* c, const uint32_t* a, uint32_t b0, uint32_t b1) {
    asm volatile("mma.sync.aligned.m16n8k16.row.col.f32.f16.f16.f32 "
                 "{%0,%1,%2,%3}, {%4,%5,%6,%7}, {%8,%9}, {%0,%1,%2,%3};"
                 : "+f"(c[0]), "+f"(c[1]), "+f"(c[2]), "+f"(c[3])
                 : "r"(a[0]), "r"(a[1]), "r"(a[2]), "r"(a[3]), "r"(b0), "r"(b1));
}

// ==================== Kernel 0: fp32 -> fp16 (+ W_cat interleave) ===========
__global__ void __launch_bounds__(256)
prepass_kernel(const float* __restrict__ X,
               const float* __restrict__ Wm, const float* __restrict__ Wg,
               const float* __restrict__ Wmod, const float* __restrict__ Wd,
               const float* __restrict__ Wout) {
    int idx = blockIdx.x * 256 + threadIdx.x;
    const float4* src;
    __half2* dst;
    if (idx < 2097152) {                          // X
        src = (const float4*)X + idx;
        dst = (__half2*)g_xh + (size_t)idx * 2;
    } else if (idx < 6291456) {                   // 4 x W -> interleaved rows ch*4+w
        int t = idx - 2097152;
        int w = t >> 20;
        int o = t & 1048575;                      // float4 idx within one W
        int row = o >> 8;                         // 0..4095 (256 float4 per 1024-row)
        int c4  = o & 255;
        const float* W = (w == 0) ? Wm : (w == 1) ? Wg : (w == 2) ? Wmod : Wd;
        src = (const float4*)W + o;
        dst = (__half2*)g_wh + ((size_t)(row * 4 + w) * 512 + c4 * 2);
    } else {                                      // W_out
        int o = idx - 6291456;
        src = (const float4*)Wout + o;
        dst = (__half2*)g_wouth + (size_t)o * 2;
    }
    float4 v = *src;
    dst[0] = __floats2half2_rn(v.x, v.y);
    dst[1] = __floats2half2_rn(v.z, v.w);
}

// ---------------- shared epilogue math ---------------------------------------
__device__ __forceinline__ void epi_one(float raw, float gp, float mp, float dpv,
                                        float bd, float al, float sl,
                                        float2* du, float2* gh) {
    float gate = 1.f / (1.f + __expf(-gp));
    float mod  = tanhf(mp);
    float z = dpv + bd;
    float Aa = -__expf(al);
    float splus = (z > 15.f) ? z : log1pf(__expf(z));
    float decay = __expf(splus * Aa);
    float u = (1.f - decay) * gate * tanhf(raw);
    float gl = 0.5f * raw * (1.f + erff(raw * 0.7071067811865475f));
    float sw = 1.f / (1.f + __expf(-sl));
    float opm = 1.f + mod;
    *du = make_float2(decay, u);
    *gh = make_float2((1.f - sw) * gl * opm, sw * opm);
}

// ==================== fp16 GEMM core pieces =================================
// CTA 256 thr (8 warps: 4m x 2n), tile 128m x 128n, warp 32x64, KT=32 halves.
// 4-stage cp.async ring; one __syncthreads per k-tile.
#define HSTR   20            // smem row stride in u32 (40 halves = 80 B)
#define STG    20480         // bytes per stage (A 10240 + B 10240)
#define GSMEM  (4 * STG)

__device__ __forceinline__ void h_load(uint32_t sb, int stage,
                                       const __half* __restrict__ A,
                                       const __half* __restrict__ B,
                                       int m0, int n0, int k0, int K, int tid) {
    uint32_t base = sb + stage * STG;
    #pragma unroll
    for (int i = 0; i < 2; i++) {
        int ch = tid + i * 256;
        int r = ch >> 2, c = ch & 3;
        CPA16(base + r * 80 + c * 16, A + (size_t)(m0 + r) * K + k0 + c * 8);
    }
    #pragma unroll
    for (int i = 0; i < 2; i++) {
        int ch = tid + i * 256;
        int r = ch >> 2, c = ch & 3;
        CPA16(base + 10240 + r * 80 + c * 16, B + (size_t)(n0 + r) * K + k0 + c * 8);
    }
}

// mainloop body macro-free: compute one 32-half k-tile from stage buffer
__device__ __forceinline__ void k_tile(const char* smem, int stage,
                                       float acc[2][8][4], int wm, int wn,
                                       int tq, int tr) {
    const uint32_t* sa = (const uint32_t*)(smem + stage * STG);
    const uint32_t* sw = (const uint32_t*)(smem + stage * STG + 10240);
    #pragma unroll
    for (int ks = 0; ks < 2; ks++) {
        uint32_t a[2][4];
        #pragma unroll
        for (int i = 0; i < 2; i++) {
            int r0 = wm * 32 + i * 16 + tq;
            int kb = ks * 8 + tr;
            a[i][0] = sa[r0 * HSTR + kb];
            a[i][1] = sa[(r0 + 8) * HSTR + kb];
            a[i][2] = sa[r0 * HSTR + kb + 4];
            a[i][3] = sa[(r0 + 8) * HSTR + kb + 4];
        }
        #pragma unroll
        for (int j = 0; j < 8; j++) {
            int nn = wn * 64 + j * 8 + tq;
            const uint32_t* bp = sw + nn * HSTR + ks * 8 + tr;
            uint32_t b0 = bp[0], b1 = bp[4];
            mma16(acc[0][j], a[0], b0, b1);
            mma16(acc[1][j], a[1], b0, b1);
        }
    }
}

// ==================== Kernel 1: proj GEMM + shuffled fused epilogue =========
// C-tile covers 32 channels x 4 interleaved weights. After mainloop, lane
// pairs (l, l^1) exchange fragments so each pair owns {raw,gate,mod,delta}.
__global__ void __launch_bounds__(256, 2)
proj_kernel(const float* __restrict__ bdel, const float* __restrict__ Alog,
            const float* __restrict__ swl) {
    extern __shared__ char smem[];
    uint32_t sb = smem_u32(smem);
    int tid = threadIdx.x, wid = tid >> 5, lane = tid & 31;
    int wm = wid & 3, wn = wid >> 2;
    int tq = lane >> 2, tr = lane & 3;
    int m0 = blockIdx.y * 128;
    int n0 = blockIdx.x * 128;
    const int K = 1024, nkt = 32;

    float acc[2][8][4];
    #pragma unroll
    for (int i = 0; i < 2; i++)
        #pragma unroll
        for (int j = 0; j < 8; j++)
            #pragma unroll
            for (int c = 0; c < 4; c++) acc[i][j][c] = 0.f;

    #pragma unroll
    for (int s = 0; s < 3; s++) {
        h_load(sb, s, g_xh, g_wh, m0, n0, s * 32, K, tid);
        CPA_COMMIT();
    }

    for (int kt = 0; kt < nkt; kt++) {
        CPA_WAIT2();
        __syncthreads();
        if (kt + 3 < nkt)
            h_load(sb, (kt + 3) & 3, g_xh, g_wh, m0, n0, (kt + 3) * 32, K, tid);
        CPA_COMMIT();
        k_tile(smem, kt & 3, acc, wm, wn, tq, tr);
    }

    // ---- fused epilogue via lane-pair shuffle ----
    int chb = ((n0 + wn * 64) >> 2) + (tr >> 1);    // channel for j=0
    float bdv[8], alv[8], slv[8];
    #pragma unroll
    for (int j = 0; j < 8; j++) {
        int ch = chb + j * 2;
        bdv[j] = __ldg(bdel + ch);
        alv[j] = __ldg(Alog + ch);
        slv[j] = __ldg(swl + ch);
    }
    bool odd = tr & 1;
    #pragma unroll
    for (int i = 0; i < 2; i++) {
        #pragma unroll
        for (int half = 0; half < 2; half++) {
            int m = m0 + wm * 32 + i * 16 + tq + half * 8;
            #pragma unroll
            for (int j = 0; j < 8; j++) {
                float c0 = acc[i][j][half * 2], c1 = acc[i][j][half * 2 + 1];
                float o0 = __shfl_xor_sync(0xFFFFFFFFu, c0, 1);
                float o1 = __shfl_xor_sync(0xFFFFFFFFu, c1, 1);
                float raw = odd ? o0 : c0;
                float gp  = odd ? o1 : c1;
                float mp  = odd ? c0 : o0;
                float dpv = odd ? c1 : o1;
                float2 du, gh;
                epi_one(raw, gp, mp, dpv, bdv[j], alv[j], slv[j], &du, &gh);
                size_t o = (size_t)m * DN + chb + j * 2;
                if (odd) g_gh[o] = gh;
                else     g_du[o] = du;
            }
        }
    }
}

// ==================== Kernel 3: output GEMM =================================
__global__ void __launch_bounds__(256, 2)
gemm_kernel(const __half* __restrict__ A, const __half* __restrict__ B,
            float* __restrict__ C, int K, int N) {
    extern __shared__ char smem[];
    uint32_t sb = smem_u32(smem);
    int tid = threadIdx.x, wid = tid >> 5, lane = tid & 31;
    int wm = wid & 3, wn = wid >> 2;
    int tq = lane >> 2, tr = lane & 3;
    int m0 = blockIdx.y * 128;
    int n0 = blockIdx.x * 128;

    float acc[2][8][4];
    #pragma unroll
    for (int i = 0; i < 2; i++)
        #pragma unroll
        for (int j = 0; j < 8; j++)
            #pragma unroll
            for (int c = 0; c < 4; c++) acc[i][j][c] = 0.f;

    #pragma unroll
    for (int s = 0; s < 3; s++) {
        h_load(sb, s, A, B, m0, n0, s * 32, K, tid);
        CPA_COMMIT();
    }

    int nkt = K >> 5;
    for (int kt = 0; kt < nkt; kt++) {
        CPA_WAIT2();
        __syncthreads();
        if (kt + 3 < nkt)
            h_load(sb, (kt + 3) & 3, A, B, m0, n0, (kt + 3) * 32, K, tid);
        CPA_COMMIT();
        k_tile(smem, kt & 3, acc, wm, wn, tq, tr);
    }

    #pragma unroll
    for (int i = 0; i < 2; i++) {
        #pragma unroll
        for (int half = 0; half < 2; half++) {
            int m = m0 + wm * 32 + i * 16 + tq + half * 8;
            float* orow = C + (size_t)m * N + n0;
            #pragma unroll
            for (int j = 0; j < 8; j++) {
                int nl = wn * 64 + j * 8 + tr * 2;
                float2 v = make_float2(acc[i][j][half * 2], acc[i][j][half * 2 + 1]);
                *(float2*)(orow + nl) = v;
            }
        }
    }
}

// ==================== Kernel 2: chunked parallel scan =======================
__global__ void __launch_bounds__(1024)
scan_kernel(const float* __restrict__ st_in, float* __restrict__ st_out, int write_state) {
    __shared__ float sP[1024], sU[1024], sC[1024];
    int tid = threadIdx.x;
    int w = tid >> 5, lane = tid & 31;
    int ch0 = blockIdx.x * 32;
    int ch = ch0 + lane;
    int batch = ch >> 12;
    int n = ch & 4095;
    size_t base = ((size_t)batch * TT) * DN + n + (size_t)w * 128 * DN;

    const float2* pdu = g_du + base;
    float P = 1.f, U = 0.f;
    #pragma unroll 8
    for (int t = 0; t < 128; t++) {
        float2 v = pdu[(size_t)t * DN];
        U = fmaf(v.x, U, v.y);
        P *= v.x;
    }
    sP[w * 32 + lane] = P;
    sU[w * 32 + lane] = U;
    __syncthreads();

    if (tid < 32) {
        float s = st_in[ch0 + tid];
        #pragma unroll
        for (int k = 0; k < 32; k++) {
            sC[k * 32 + tid] = s;
            s = fmaf(sP[k * 32 + tid], s, sU[k * 32 + tid]);
        }
        if (write_state) st_out[ch0 + tid] = s;
    }
    __syncthreads();

    float s = sC[w * 32 + lane];
    const float2* pgh = g_gh + base;
    __half* py = g_yh + base;
    #pragma unroll 4
    for (int t = 0; t < 128; t++) {
        float2 v  = pdu[(size_t)t * DN];
        float2 gh = pgh[(size_t)t * DN];
        s = fmaf(v.x, s, v.y);
        py[(size_t)t * DN] = __float2half_rn(fmaf(gh.y, s, gh.x));
    }
}

// ==================== launch ================================================
extern "C" void kernel_launch(void* const* d_in, const int* in_sizes, int n_in,
                              void* d_out, int out_size) {
    const float* x    = (const float*)d_in[0];
    const float* st   = (const float*)d_in[1];
    const float* Wm   = (const float*)d_in[2];
    const float* Wg   = (const float*)d_in[3];
    const float* Wmod = (const float*)d_in[4];
    const float* Wout = (const float*)d_in[5];
    const float* Wd   = (const float*)d_in[6];
    const float* bdel = (const float*)d_in[7];
    const float* Alog = (const float*)d_in[8];
    const float* swl  = (const float*)d_in[9];
    float* out = (float*)d_out;

    cudaFuncSetAttribute(proj_kernel, cudaFuncAttributeMaxDynamicSharedMemorySize, GSMEM);
    cudaFuncSetAttribute(gemm_kernel, cudaFuncAttributeMaxDynamicSharedMemorySize, GSMEM);

    static __half* p_yh = nullptr;
    static __half* p_wouth = nullptr;
    if (!p_yh) {
        void* tmp;
        cudaGetSymbolAddress(&tmp, g_yh);    p_yh = (__half*)tmp;
        cudaGetSymbolAddress(&tmp, g_wouth); p_wouth = (__half*)tmp;
    }

    prepass_kernel<<<28672, 256>>>(x, Wm, Wg, Wmod, Wd, Wout);

    // proj + fused epilogue: du/gh[8192,4096] from Xh[8192,1024] @ Wcat_i[16384,1024]^T
    proj_kernel<<<dim3(128, 64), 256, GSMEM>>>(bdel, Alog, swl);

    int has_state = (out_size >= MTOT * DM + BB * DN) ? 1 : 0;
    scan_kernel<<<256, 1024>>>(st, out + (size_t)MTOT * DM, has_state);

    // out[8192,1024] = yh[8192,4096] @ Wouth[1024,4096]^T
    gemm_kernel<<<dim3(8, 64), 256, GSMEM>>>(p_yh, p_wouth, out, 4096, 1024);
}

// round 13
// speedup vs baseline: 1.1476x; 1.1476x over previous
#include <cuda_runtime.h>
#include <cuda_fp16.h>
#include <cstdint>

#define DM 1024
#define DN 4096
#define BB 2
#define TT 4096
#define MTOT 8192   // BB*TT

// ---------------- scratch (device globals) ----------------------------------
__device__ __half  g_xh[8388608];      // fp16 X [8192,1024]
__device__ __half  g_wh[16777216];     // fp16 W_cat interleaved [16384,1024]; row = ch*4+w
__device__ __half  g_wouth[4194304];   // fp16 W_out [1024,4096]
__device__ float2  g_du[33554432];     // {decay, update} [8192,4096]
__device__ float2  g_gh[33554432];     // {g, h}          [8192,4096]
__device__ __half  g_yh[33554432];     // fp16 y          [8192,4096]

// ---------------- helpers ----------------------------------------------------
__device__ __forceinline__ uint32_t smem_u32(const void* p) {
    uint32_t a;
    asm("{ .reg .u64 t; cvta.to.shared.u64 t, %1; cvt.u32.u64 %0, t; }" : "=r"(a) : "l"(p));
    return a;
}

#define CPA16(dst, src) asm volatile("cp.async.cg.shared.global [%0], [%1], 16;" :: "r"(dst), "l"(src) : "memory")
#define CPA_COMMIT()    asm volatile("cp.async.commit_group;" ::: "memory")
#define CPA_WAIT2()     asm volatile("cp.async.wait_group 2;" ::: "memory")

// m16n8k16 fp16 mma, fp32 accum
__device__ __forceinline__ void mma16(float* c, const uint32_t* a, uint32_t b0, uint32_t b1) {
    asm volatile("mma.sync.aligned.m16n8k16.row.col.f32.f16.f16.f32 "
                 "{%0,%1,%2,%3}, {%4,%5,%6,%7}, {%8,%9}, {%0,%1,%2,%3};"
                 : "+f"(c[0]), "+f"(c[1]), "+f"(c[2]), "+f"(c[3])
                 : "r"(a[0]), "r"(a[1]), "r"(a[2]), "r"(a[3]), "r"(b0), "r"(b1));
}

__device__ __forceinline__ void ldsm4(uint32_t* r, uint32_t addr) {
    asm volatile("ldmatrix.sync.aligned.m8n8.x4.shared.b16 {%0,%1,%2,%3}, [%4];"
                 : "=r"(r[0]), "=r"(r[1]), "=r"(r[2]), "=r"(r[3]) : "r"(addr));
}

// ==================== Kernel 0: fp32 -> fp16 (+ W_cat interleave) ===========
__global__ void __launch_bounds__(256)
prepass_kernel(const float* __restrict__ X,
               const float* __restrict__ Wm, const float* __restrict__ Wg,
               const float* __restrict__ Wmod, const float* __restrict__ Wd,
               const float* __restrict__ Wout) {
    int idx = blockIdx.x * 256 + threadIdx.x;
    const float4* src;
    __half2* dst;
    if (idx < 2097152) {                          // X
        src = (const float4*)X + idx;
        dst = (__half2*)g_xh + (size_t)idx * 2;
    } else if (idx < 6291456) {                   // 4 x W -> interleaved rows ch*4+w
        int t = idx - 2097152;
        int w = t >> 20;
        int o = t & 1048575;
        int row = o >> 8;
        int c4  = o & 255;
        const float* W = (w == 0) ? Wm : (w == 1) ? Wg : (w == 2) ? Wmod : Wd;
        src = (const float4*)W + o;
        dst = (__half2*)g_wh + ((size_t)(row * 4 + w) * 512 + c4 * 2);
    } else {                                      // W_out
        int o = idx - 6291456;
        src = (const float4*)Wout + o;
        dst = (__half2*)g_wouth + (size_t)o * 2;
    }
    float4 v = *src;
    dst[0] = __floats2half2_rn(v.x, v.y);
    dst[1] = __floats2half2_rn(v.z, v.w);
}

// ---------------- shared epilogue math ---------------------------------------
__device__ __forceinline__ void epi_one(float raw, float gp, float mp, float dpv,
                                        float bd, float al, float sl,
                                        float2* du, float2* gh) {
    float gate = 1.f / (1.f + __expf(-gp));
    float mod  = tanhf(mp);
    float z = dpv + bd;
    float Aa = -__expf(al);
    float splus = (z > 15.f) ? z : log1pf(__expf(z));
    float decay = __expf(splus * Aa);
    float u = (1.f - decay) * gate * tanhf(raw);
    float gl = 0.5f * raw * (1.f + erff(raw * 0.7071067811865475f));
    float sw = 1.f / (1.f + __expf(-sl));
    float opm = 1.f + mod;
    *du = make_float2(decay, u);
    *gh = make_float2((1.f - sw) * gl * opm, sw * opm);
}

// ==================== fp16 GEMM core pieces =================================
// CTA 256 thr (8 warps: 4m x 2n), tile 128m x 128n, warp 32x64, KT=32 halves.
// 4-stage cp.async ring; ldmatrix fragment loads, batched per k16-step.
#define STG    20480         // bytes per stage (A 10240 + B 10240)
#define GSMEM  (4 * STG)

__device__ __forceinline__ void h_load(uint32_t sb, int stage,
                                       const __half* __restrict__ A,
                                       const __half* __restrict__ B,
                                       int m0, int n0, int k0, int K, int tid) {
    uint32_t base = sb + stage * STG;
    #pragma unroll
    for (int i = 0; i < 2; i++) {
        int ch = tid + i * 256;
        int r = ch >> 2, c = ch & 3;
        CPA16(base + r * 80 + c * 16, A + (size_t)(m0 + r) * K + k0 + c * 8);
    }
    #pragma unroll
    for (int i = 0; i < 2; i++) {
        int ch = tid + i * 256;
        int r = ch >> 2, c = ch & 3;
        CPA16(base + 10240 + r * 80 + c * 16, B + (size_t)(n0 + r) * K + k0 + c * 8);
    }
}

// per-thread invariant ldmatrix offsets
struct LdsmOff { uint32_t a0, a1, b[4]; };

__device__ __forceinline__ LdsmOff ldsm_offsets(int wm, int wn, int lane) {
    LdsmOff o;
    // A: 16x16 quad; lanes 0-15 -> rows (k-half 0), lanes 16-31 -> same rows (k-half 1)
    o.a0 = (uint32_t)((wm * 32 + (lane & 15)) * 80 + (lane >> 4) * 16);
    o.a1 = o.a0 + 16 * 80;
    // B: per j-pair: lanes 0-7 j_even/half0, 8-15 j_even/half1, 16-23 j_odd/half0, 24-31 j_odd/half1
    #pragma unroll
    for (int j2 = 0; j2 < 4; j2++) {
        int row = wn * 64 + j2 * 16 + ((lane >> 4) & 1) * 8 + (lane & 7);
        o.b[j2] = (uint32_t)(10240 + row * 80 + ((lane >> 3) & 1) * 16);
    }
    return o;
}

__device__ __forceinline__ void k_tile(uint32_t sb, int stage, float acc[2][8][4],
                                       const LdsmOff& off) {
    uint32_t s0 = sb + stage * STG;
    #pragma unroll
    for (int ks = 0; ks < 2; ks++) {
        uint32_t kd = ks * 32;
        uint32_t a0[4], a1[4], b[4][4];
        ldsm4(a0, s0 + off.a0 + kd);
        ldsm4(a1, s0 + off.a1 + kd);
        #pragma unroll
        for (int j2 = 0; j2 < 4; j2++) ldsm4(b[j2], s0 + off.b[j2] + kd);
        #pragma unroll
        for (int j2 = 0; j2 < 4; j2++) {
            mma16(acc[0][2 * j2],     a0, b[j2][0], b[j2][1]);
            mma16(acc[1][2 * j2],     a1, b[j2][0], b[j2][1]);
            mma16(acc[0][2 * j2 + 1], a0, b[j2][2], b[j2][3]);
            mma16(acc[1][2 * j2 + 1], a1, b[j2][2], b[j2][3]);
        }
    }
}

// ==================== Kernel 1: proj GEMM + shuffled fused epilogue =========
__global__ void __launch_bounds__(256, 2)
proj_kernel(const float* __restrict__ bdel, const float* __restrict__ Alog,
            const float* __restrict__ swl) {
    extern __shared__ char smem[];
    uint32_t sb = smem_u32(smem);
    int tid = threadIdx.x, wid = tid >> 5, lane = tid & 31;
    int wm = wid & 3, wn = wid >> 2;
    int tq = lane >> 2, tr = lane & 3;
    int m0 = blockIdx.y * 128;
    int n0 = blockIdx.x * 128;
    const int K = 1024, nkt = 32;
    LdsmOff off = ldsm_offsets(wm, wn, lane);

    float acc[2][8][4];
    #pragma unroll
    for (int i = 0; i < 2; i++)
        #pragma unroll
        for (int j = 0; j < 8; j++)
            #pragma unroll
            for (int c = 0; c < 4; c++) acc[i][j][c] = 0.f;

    #pragma unroll
    for (int s = 0; s < 3; s++) {
        h_load(sb, s, g_xh, g_wh, m0, n0, s * 32, K, tid);
        CPA_COMMIT();
    }

    for (int kt = 0; kt < nkt; kt++) {
        CPA_WAIT2();
        __syncthreads();
        if (kt + 3 < nkt)
            h_load(sb, (kt + 3) & 3, g_xh, g_wh, m0, n0, (kt + 3) * 32, K, tid);
        CPA_COMMIT();
        k_tile(sb, kt & 3, acc, off);
    }

    // ---- fused epilogue via lane-pair shuffle ----
    int chb = ((n0 + wn * 64) >> 2) + (tr >> 1);
    float bdv[8], alv[8], slv[8];
    #pragma unroll
    for (int j = 0; j < 8; j++) {
        int ch = chb + j * 2;
        bdv[j] = __ldg(bdel + ch);
        alv[j] = __ldg(Alog + ch);
        slv[j] = __ldg(swl + ch);
    }
    bool odd = tr & 1;
    #pragma unroll
    for (int i = 0; i < 2; i++) {
        #pragma unroll
        for (int half = 0; half < 2; half++) {
            int m = m0 + wm * 32 + i * 16 + tq + half * 8;
            #pragma unroll
            for (int j = 0; j < 8; j++) {
                float c0 = acc[i][j][half * 2], c1 = acc[i][j][half * 2 + 1];
                float o0 = __shfl_xor_sync(0xFFFFFFFFu, c0, 1);
                float o1 = __shfl_xor_sync(0xFFFFFFFFu, c1, 1);
                float raw = odd ? o0 : c0;
                float gp  = odd ? o1 : c1;
                float mp  = odd ? c0 : o0;
                float dpv = odd ? c1 : o1;
                float2 du, gh;
                epi_one(raw, gp, mp, dpv, bdv[j], alv[j], slv[j], &du, &gh);
                size_t o = (size_t)m * DN + chb + j * 2;
                if (odd) g_gh[o] = gh;
                else     g_du[o] = du;
            }
        }
    }
}

// ==================== Kernel 3: output GEMM =================================
__global__ void __launch_bounds__(256, 2)
gemm_kernel(const __half* __restrict__ A, const __half* __restrict__ B,
            float* __restrict__ C, int K, int N) {
    extern __shared__ char smem[];
    uint32_t sb = smem_u32(smem);
    int tid = threadIdx.x, wid = tid >> 5, lane = tid & 31;
    int wm = wid & 3, wn = wid >> 2;
    int tq = lane >> 2, tr = lane & 3;
    int m0 = blockIdx.y * 128;
    int n0 = blockIdx.x * 128;
    LdsmOff off = ldsm_offsets(wm, wn, lane);

    float acc[2][8][4];
    #pragma unroll
    for (int i = 0; i < 2; i++)
        #pragma unroll
        for (int j = 0; j < 8; j++)
            #pragma unroll
            for (int c = 0; c < 4; c++) acc[i][j][c] = 0.f;

    #pragma unroll
    for (int s = 0; s < 3; s++) {
        h_load(sb, s, A, B, m0, n0, s * 32, K, tid);
        CPA_COMMIT();
    }

    int nkt = K >> 5;
    for (int kt = 0; kt < nkt; kt++) {
        CPA_WAIT2();
        __syncthreads();
        if (kt + 3 < nkt)
            h_load(sb, (kt + 3) & 3, A, B, m0, n0, (kt + 3) * 32, K, tid);
        CPA_COMMIT();
        k_tile(sb, kt & 3, acc, off);
    }

    #pragma unroll
    for (int i = 0; i < 2; i++) {
        #pragma unroll
        for (int half = 0; half < 2; half++) {
            int m = m0 + wm * 32 + i * 16 + tq + half * 8;
            float* orow = C + (size_t)m * N + n0;
            #pragma unroll
            for (int j = 0; j < 8; j++) {
                int nl = wn * 64 + j * 8 + tr * 2;
                float2 v = make_float2(acc[i][j][half * 2], acc[i][j][half * 2 + 1]);
                *(float2*)(orow + nl) = v;
            }
        }
    }
}

// ==================== Kernel 2: chunked parallel scan =======================
__global__ void __launch_bounds__(1024)
scan_kernel(const float* __restrict__ st_in, float* __restrict__ st_out, int write_state) {
    __shared__ float sP[1024], sU[1024], sC[1024];
    int tid = threadIdx.x;
    int w = tid >> 5, lane = tid & 31;
    int ch0 = blockIdx.x * 32;
    int ch = ch0 + lane;
    int batch = ch >> 12;
    int n = ch & 4095;
    size_t base = ((size_t)batch * TT) * DN + n + (size_t)w * 128 * DN;

    const float2* pdu = g_du + base;
    float P = 1.f, U = 0.f;
    #pragma unroll 8
    for (int t = 0; t < 128; t++) {
        float2 v = pdu[(size_t)t * DN];
        U = fmaf(v.x, U, v.y);
        P *= v.x;
    }
    sP[w * 32 + lane] = P;
    sU[w * 32 + lane] = U;
    __syncthreads();

    if (tid < 32) {
        float s = st_in[ch0 + tid];
        #pragma unroll
        for (int k = 0; k < 32; k++) {
            sC[k * 32 + tid] = s;
            s = fmaf(sP[k * 32 + tid], s, sU[k * 32 + tid]);
        }
        if (write_state) st_out[ch0 + tid] = s;
    }
    __syncthreads();

    float s = sC[w * 32 + lane];
    const float2* pgh = g_gh + base;
    __half* py = g_yh + base;
    #pragma unroll 4
    for (int t = 0; t < 128; t++) {
        float2 v  = pdu[(size_t)t * DN];
        float2 gh = pgh[(size_t)t * DN];
        s = fmaf(v.x, s, v.y);
        py[(size_t)t * DN] = __float2half_rn(fmaf(gh.y, s, gh.x));
    }
}

// ==================== launch ================================================
extern "C" void kernel_launch(void* const* d_in, const int* in_sizes, int n_in,
                              void* d_out, int out_size) {
    const float* x    = (const float*)d_in[0];
    const float* st   = (const float*)d_in[1];
    const float* Wm   = (const float*)d_in[2];
    const float* Wg   = (const float*)d_in[3];
    const float* Wmod = (const float*)d_in[4];
    const float* Wout = (const float*)d_in[5];
    const float* Wd   = (const float*)d_in[6];
    const float* bdel = (const float*)d_in[7];
    const float* Alog = (const float*)d_in[8];
    const float* swl  = (const float*)d_in[9];
    float* out = (float*)d_out;

    cudaFuncSetAttribute(proj_kernel, cudaFuncAttributeMaxDynamicSharedMemorySize, GSMEM);
    cudaFuncSetAttribute(gemm_kernel, cudaFuncAttributeMaxDynamicSharedMemorySize, GSMEM);

    static __half* p_yh = nullptr;
    static __half* p_wouth = nullptr;
    if (!p_yh) {
        void* tmp;
        cudaGetSymbolAddress(&tmp, g_yh);    p_yh = (__half*)tmp;
        cudaGetSymbolAddress(&tmp, g_wouth); p_wouth = (__half*)tmp;
    }

    prepass_kernel<<<28672, 256>>>(x, Wm, Wg, Wmod, Wd, Wout);

    // proj + fused epilogue: du/gh[8192,4096] from Xh[8192,1024] @ Wcat_i[16384,1024]^T
    proj_kernel<<<dim3(128, 64), 256, GSMEM>>>(bdel, Alog, swl);

    int has_state = (out_size >= MTOT * DM + BB * DN) ? 1 : 0;
    scan_kernel<<<256, 1024>>>(st, out + (size_t)MTOT * DM, has_state);

    // out[8192,1024] = yh[8192,4096] @ Wouth[1024,4096]^T
    gemm_kernel<<<dim3(8, 64), 256, GSMEM>>>(p_yh, p_wouth, out, 4096, 1024);
}

// round 17
// speedup vs baseline: 1.1490x; 1.0012x over previous
#include <cuda_runtime.h>
#include <cuda_fp16.h>
#include <cstdint>

#define DM 1024
#define DN 4096
#define BB 2
#define TT 4096
#define MTOT 8192   // BB*TT

// ---------------- scratch (device globals) ----------------------------------
__device__ __half  g_xh[8388608];      // fp16 X [8192,1024]
__device__ __half  g_wh[16777216];     // fp16 W_cat interleaved [16384,1024]; row = ch*4+w
__device__ __half  g_wouth[4194304];   // fp16 W_out [1024,4096]
__device__ float2  g_du[33554432];     // {decay, update} [8192,4096]
__device__ float2  g_gh[33554432];     // {g, h}          [8192,4096]
__device__ __half  g_yh[33554432];     // fp16 y          [8192,4096]

// ---------------- helpers ----------------------------------------------------
__device__ __forceinline__ uint32_t smem_u32(const void* p) {
    uint32_t a;
    asm("{ .reg .u64 t; cvta.to.shared.u64 t, %1; cvt.u32.u64 %0, t; }" : "=r"(a) : "l"(p));
    return a;
}

#define CPA16(dst, src) asm volatile("cp.async.cg.shared.global [%0], [%1], 16;" :: "r"(dst), "l"(src) : "memory")
#define CPA_COMMIT()    asm volatile("cp.async.commit_group;" ::: "memory")
#define CPA_WAIT2()     asm volatile("cp.async.wait_group 2;" ::: "memory")

// m16n8k16 fp16 mma, fp32 accum
__device__ __forceinline__ void mma16(float* c, const uint32_t* a, uint32_t b0, uint32_t b1) {
    asm volatile("mma.sync.aligned.m16n8k16.row.col.f32.f16.f16.f32 "
                 "{%0,%1,%2,%3}, {%4,%5,%6,%7}, {%8,%9}, {%0,%1,%2,%3};"
                 : "+f"(c[0]), "+f"(c[1]), "+f"(c[2]), "+f"(c[3])
                 : "r"(a[0]), "r"(a[1]), "r"(a[2]), "r"(a[3]), "r"(b0), "r"(b1));
}

__device__ __forceinline__ void ldsm4(uint32_t* r, uint32_t addr) {
    asm volatile("ldmatrix.sync.aligned.m8n8.x4.shared.b16 {%0,%1,%2,%3}, [%4];"
                 : "=r"(r[0]), "=r"(r[1]), "=r"(r[2]), "=r"(r[3]) : "r"(addr));
}

// ==================== Kernel 0: fp32 -> fp16 (+ W_cat interleave) ===========
__global__ void __launch_bounds__(256)
prepass_kernel(const float* __restrict__ X,
               const float* __restrict__ Wm, const float* __restrict__ Wg,
               const float* __restrict__ Wmod, const float* __restrict__ Wd,
               const float* __restrict__ Wout) {
    int idx = blockIdx.x * 256 + threadIdx.x;
    const float4* src;
    __half2* dst;
    if (idx < 2097152) {                          // X
        src = (const float4*)X + idx;
        dst = (__half2*)g_xh + (size_t)idx * 2;
    } else if (idx < 6291456) {                   // 4 x W -> interleaved rows ch*4+w
        int t = idx - 2097152;
        int w = t >> 20;
        int o = t & 1048575;
        int row = o >> 8;
        int c4  = o & 255;
        const float* W = (w == 0) ? Wm : (w == 1) ? Wg : (w == 2) ? Wmod : Wd;
        src = (const float4*)W + o;
        dst = (__half2*)g_wh + ((size_t)(row * 4 + w) * 512 + c4 * 2);
    } else {                                      // W_out
        int o = idx - 6291456;
        src = (const float4*)Wout + o;
        dst = (__half2*)g_wouth + (size_t)o * 2;
    }
    float4 v = *src;
    dst[0] = __floats2half2_rn(v.x, v.y);
    dst[1] = __floats2half2_rn(v.z, v.w);
}

// ---------------- shared epilogue math ---------------------------------------
__device__ __forceinline__ void epi_one(float raw, float gp, float mp, float dpv,
                                        float bd, float al, float sl,
                                        float2* du, float2* gh) {
    float gate = 1.f / (1.f + __expf(-gp));
    float mod  = tanhf(mp);
    float z = dpv + bd;
    float Aa = -__expf(al);
    float splus = (z > 15.f) ? z : log1pf(__expf(z));
    float decay = __expf(splus * Aa);
    float u = (1.f - decay) * gate * tanhf(raw);
    float gl = 0.5f * raw * (1.f + erff(raw * 0.7071067811865475f));
    float sw = 1.f / (1.f + __expf(-sl));
    float opm = 1.f + mod;
    *du = make_float2(decay, u);
    *gh = make_float2((1.f - sw) * gl * opm, sw * opm);
}

// ==================== fp16 GEMM core pieces =================================
// CTA 256 thr (8 warps: 4m x 2n), tile 128m x 128n, warp 32x64, KT=32 halves.
// 4-stage cp.async ring; ldmatrix, software-pipelined across the two k16 steps.
#define STG    20480         // bytes per stage (A 10240 + B 10240)
#define GSMEM  (4 * STG)

__device__ __forceinline__ void h_load(uint32_t sb, int stage,
                                       const __half* __restrict__ A,
                                       const __half* __restrict__ B,
                                       int m0, int n0, int k0, int K, int tid) {
    uint32_t base = sb + stage * STG;
    #pragma unroll
    for (int i = 0; i < 2; i++) {
        int ch = tid + i * 256;
        int r = ch >> 2, c = ch & 3;
        CPA16(base + r * 80 + c * 16, A + (size_t)(m0 + r) * K + k0 + c * 8);
    }
    #pragma unroll
    for (int i = 0; i < 2; i++) {
        int ch = tid + i * 256;
        int r = ch >> 2, c = ch & 3;
        CPA16(base + 10240 + r * 80 + c * 16, B + (size_t)(n0 + r) * K + k0 + c * 8);
    }
}

// per-thread invariant ldmatrix offsets
struct LdsmOff { uint32_t a0, a1, b[4]; };

__device__ __forceinline__ LdsmOff ldsm_offsets(int wm, int wn, int lane) {
    LdsmOff o;
    o.a0 = (uint32_t)((wm * 32 + (lane & 15)) * 80 + (lane >> 4) * 16);
    o.a1 = o.a0 + 16 * 80;
    #pragma unroll
    for (int j2 = 0; j2 < 4; j2++) {
        int row = wn * 64 + j2 * 16 + ((lane >> 4) & 1) * 8 + (lane & 7);
        o.b[j2] = (uint32_t)(10240 + row * 80 + ((lane >> 3) & 1) * 16);
    }
    return o;
}

// software-pipelined k-tile: ks1 fragment loads are issued under ks0 MMAs
__device__ __forceinline__ void k_tile(uint32_t sb, int stage, float acc[2][8][4],
                                       const LdsmOff& off) {
    uint32_t s0 = sb + stage * STG;
    uint32_t a0[4], a1[4], b0[4], b1[4], b2[4], b3[4];
    uint32_t c0[4], c1[4], d0[4], d1[4], d2[4], d3[4];

    // ks0 loads + early ks1 A loads
    ldsm4(b0, s0 + off.b[0]);
    ldsm4(b1, s0 + off.b[1]);
    ldsm4(a0, s0 + off.a0);
    ldsm4(a1, s0 + off.a1);
    ldsm4(b2, s0 + off.b[2]);
    ldsm4(b3, s0 + off.b[3]);
    ldsm4(c0, s0 + off.a0 + 32);
    ldsm4(c1, s0 + off.a1 + 32);

    // MMA ks0, j2 = 0,1
    mma16(acc[0][0], a0, b0[0], b0[1]);
    mma16(acc[1][0], a1, b0[0], b0[1]);
    mma16(acc[0][1], a0, b0[2], b0[3]);
    mma16(acc[1][1], a1, b0[2], b0[3]);
    mma16(acc[0][2], a0, b1[0], b1[1]);
    mma16(acc[1][2], a1, b1[0], b1[1]);
    mma16(acc[0][3], a0, b1[2], b1[3]);
    mma16(acc[1][3], a1, b1[2], b1[3]);

    // ks1 B loads (first half) under ks0 j2=2,3 MMAs
    ldsm4(d0, s0 + off.b[0] + 32);
    ldsm4(d1, s0 + off.b[1] + 32);

    mma16(acc[0][4], a0, b2[0], b2[1]);
    mma16(acc[1][4], a1, b2[0], b2[1]);
    mma16(acc[0][5], a0, b2[2], b2[3]);
    mma16(acc[1][5], a1, b2[2], b2[3]);
    mma16(acc[0][6], a0, b3[0], b3[1]);
    mma16(acc[1][6], a1, b3[0], b3[1]);
    mma16(acc[0][7], a0, b3[2], b3[3]);
    mma16(acc[1][7], a1, b3[2], b3[3]);

    // ks1 B loads (second half)
    ldsm4(d2, s0 + off.b[2] + 32);
    ldsm4(d3, s0 + off.b[3] + 32);

    // MMA ks1, all j
    mma16(acc[0][0], c0, d0[0], d0[1]);
    mma16(acc[1][0], c1, d0[0], d0[1]);
    mma16(acc[0][1], c0, d0[2], d0[3]);
    mma16(acc[1][1], c1, d0[2], d0[3]);
    mma16(acc[0][2], c0, d1[0], d1[1]);
    mma16(acc[1][2], c1, d1[0], d1[1]);
    mma16(acc[0][3], c0, d1[2], d1[3]);
    mma16(acc[1][3], c1, d1[2], d1[3]);
    mma16(acc[0][4], c0, d2[0], d2[1]);
    mma16(acc[1][4], c1, d2[0], d2[1]);
    mma16(acc[0][5], c0, d2[2], d2[3]);
    mma16(acc[1][5], c1, d2[2], d2[3]);
    mma16(acc[0][6], c0, d3[0], d3[1]);
    mma16(acc[1][6], c1, d3[0], d3[1]);
    mma16(acc[0][7], c0, d3[2], d3[3]);
    mma16(acc[1][7], c1, d3[2], d3[3]);
}

// ==================== Kernel 1: proj GEMM + shuffled fused epilogue =========
__global__ void __launch_bounds__(256, 2)
proj_kernel(const float* __restrict__ bdel, const float* __restrict__ Alog,
            const float* __restrict__ swl) {
    extern __shared__ char smem[];
    uint32_t sb = smem_u32(smem);
    int tid = threadIdx.x, wid = tid >> 5, lane = tid & 31;
    int wm = wid & 3, wn = wid >> 2;
    int tq = lane >> 2, tr = lane & 3;
    int m0 = blockIdx.y * 128;
    int n0 = blockIdx.x * 128;
    const int K = 1024, nkt = 32;
    LdsmOff off = ldsm_offsets(wm, wn, lane);

    float acc[2][8][4];
    #pragma unroll
    for (int i = 0; i < 2; i++)
        #pragma unroll
        for (int j = 0; j < 8; j++)
            #pragma unroll
            for (int c = 0; c < 4; c++) acc[i][j][c] = 0.f;

    #pragma unroll
    for (int s = 0; s < 3; s++) {
        h_load(sb, s, g_xh, g_wh, m0, n0, s * 32, K, tid);
        CPA_COMMIT();
    }

    for (int kt = 0; kt < nkt; kt++) {
        CPA_WAIT2();
        __syncthreads();
        if (kt + 3 < nkt)
            h_load(sb, (kt + 3) & 3, g_xh, g_wh, m0, n0, (kt + 3) * 32, K, tid);
        CPA_COMMIT();
        k_tile(sb, kt & 3, acc, off);
    }

    // ---- fused epilogue via lane-pair shuffle ----
    int chb = ((n0 + wn * 64) >> 2) + (tr >> 1);
    float bdv[8], alv[8], slv[8];
    #pragma unroll
    for (int j = 0; j < 8; j++) {
        int ch = chb + j * 2;
        bdv[j] = __ldg(bdel + ch);
        alv[j] = __ldg(Alog + ch);
        slv[j] = __ldg(swl + ch);
    }
    bool odd = tr & 1;
    #pragma unroll
    for (int i = 0; i < 2; i++) {
        #pragma unroll
        for (int half = 0; half < 2; half++) {
            int m = m0 + wm * 32 + i * 16 + tq + half * 8;
            #pragma unroll
            for (int j = 0; j < 8; j++) {
                float c0 = acc[i][j][half * 2], c1 = acc[i][j][half * 2 + 1];
                float o0 = __shfl_xor_sync(0xFFFFFFFFu, c0, 1);
                float o1 = __shfl_xor_sync(0xFFFFFFFFu, c1, 1);
                float raw = odd ? o0 : c0;
                float gp  = odd ? o1 : c1;
                float mp  = odd ? c0 : o0;
                float dpv = odd ? c1 : o1;
                float2 du, gh;
                epi_one(raw, gp, mp, dpv, bdv[j], alv[j], slv[j], &du, &gh);
                size_t o = (size_t)m * DN + chb + j * 2;
                if (odd) g_gh[o] = gh;
                else     g_du[o] = du;
            }
        }
    }
}

// ==================== Kernel 3: output GEMM =================================
__global__ void __launch_bounds__(256, 2)
gemm_kernel(const __half* __restrict__ A, const __half* __restrict__ B,
            float* __restrict__ C, int K, int N) {
    extern __shared__ char smem[];
    uint32_t sb = smem_u32(smem);
    int tid = threadIdx.x, wid = tid >> 5, lane = tid & 31;
    int wm = wid & 3, wn = wid >> 2;
    int tq = lane >> 2, tr = lane & 3;
    int m0 = blockIdx.y * 128;
    int n0 = blockIdx.x * 128;
    LdsmOff off = ldsm_offsets(wm, wn, lane);

    float acc[2][8][4];
    #pragma unroll
    for (int i = 0; i < 2; i++)
        #pragma unroll
        for (int j = 0; j < 8; j++)
            #pragma unroll
            for (int c = 0; c < 4; c++) acc[i][j][c] = 0.f;

    #pragma unroll
    for (int s = 0; s < 3; s++) {
        h_load(sb, s, A, B, m0, n0, s * 32, K, tid);
        CPA_COMMIT();
    }

    int nkt = K >> 5;
    for (int kt = 0; kt < nkt; kt++) {
        CPA_WAIT2();
        __syncthreads();
        if (kt + 3 < nkt)
            h_load(sb, (kt + 3) & 3, A, B, m0, n0, (kt + 3) * 32, K, tid);
        CPA_COMMIT();
        k_tile(sb, kt & 3, acc, off);
    }

    #pragma unroll
    for (int i = 0; i < 2; i++) {
        #pragma unroll
        for (int half = 0; half < 2; half++) {
            int m = m0 + wm * 32 + i * 16 + tq + half * 8;
            float* orow = C + (size_t)m * N + n0;
            #pragma unroll
            for (int j = 0; j < 8; j++) {
                int nl = wn * 64 + j * 8 + tr * 2;
                float2 v = make_float2(acc[i][j][half * 2], acc[i][j][half * 2 + 1]);
                *(float2*)(orow + nl) = v;
            }
        }
    }
}

// ==================== Kernel 2: chunked parallel scan =======================
__global__ void __launch_bounds__(1024)
scan_kernel(const float* __restrict__ st_in, float* __restrict__ st_out, int write_state) {
    __shared__ float sP[1024], sU[1024], sC[1024];
    int tid = threadIdx.x;
    int w = tid >> 5, lane = tid & 31;
    int ch0 = blockIdx.x * 32;
    int ch = ch0 + lane;
    int batch = ch >> 12;
    int n = ch & 4095;
    size_t base = ((size_t)batch * TT) * DN + n + (size_t)w * 128 * DN;

    const float2* pdu = g_du + base;
    float P = 1.f, U = 0.f;
    #pragma unroll 8
    for (int t = 0; t < 128; t++) {
        float2 v = pdu[(size_t)t * DN];
        U = fmaf(v.x, U, v.y);
        P *= v.x;
    }
    sP[w * 32 + lane] = P;
    sU[w * 32 + lane] = U;
    __syncthreads();

    if (tid < 32) {
        float s = st_in[ch0 + tid];
        #pragma unroll
        for (int k = 0; k < 32; k++) {
            sC[k * 32 + tid] = s;
            s = fmaf(sP[k * 32 + tid], s, sU[k * 32 + tid]);
        }
        if (write_state) st_out[ch0 + tid] = s;
    }
    __syncthreads();

    float s = sC[w * 32 + lane];
    const float2* pgh = g_gh + base;
    __half* py = g_yh + base;
    #pragma unroll 4
    for (int t = 0; t < 128; t++) {
        float2 v  = pdu[(size_t)t * DN];
        float2 gh = pgh[(size_t)t * DN];
        s = fmaf(v.x, s, v.y);
        py[(size_t)t * DN] = __float2half_rn(fmaf(gh.y, s, gh.x));
    }
}

// ==================== launch ================================================
extern "C" void kernel_launch(void* const* d_in, const int* in_sizes, int n_in,
                              void* d_out, int out_size) {
    const float* x    = (const float*)d_in[0];
    const float* st   = (const float*)d_in[1];
    const float* Wm   = (const float*)d_in[2];
    const float* Wg   = (const float*)d_in[3];
    const float* Wmod = (const float*)d_in[4];
    const float* Wd   = (const float*)d_in[6];
    const float* Wout = (const float*)d_in[5];
    const float* bdel = (const float*)d_in[7];
    const float* Alog = (const float*)d_in[8];
    const float* swl  = (const float*)d_in[9];
    float* out = (float*)d_out;

    cudaFuncSetAttribute(proj_kernel, cudaFuncAttributeMaxDynamicSharedMemorySize, GSMEM);
    cudaFuncSetAttribute(gemm_kernel, cudaFuncAttributeMaxDynamicSharedMemorySize, GSMEM);

    static __half* p_yh = nullptr;
    static __half* p_wouth = nullptr;
    if (!p_yh) {
        void* tmp;
        cudaGetSymbolAddress(&tmp, g_yh);    p_yh = (__half*)tmp;
        cudaGetSymbolAddress(&tmp, g_wouth); p_wouth = (__half*)tmp;
    }

    prepass_kernel<<<28672, 256>>>(x, Wm, Wg, Wmod, Wd, Wout);

    // proj + fused epilogue: du/gh[8192,4096] from Xh[8192,1024] @ Wcat_i[16384,1024]^T
    proj_kernel<<<dim3(128, 64), 256, GSMEM>>>(bdel, Alog, swl);

    int has_state = (out_size >= MTOT * DM + BB * DN) ? 1 : 0;
    scan_kernel<<<256, 1024>>>(st, out + (size_t)MTOT * DM, has_state);

    // out[8192,1024] = yh[8192,4096] @ Wouth[1024,4096]^T
    gemm_kernel<<<dim3(8, 64), 256, GSMEM>>>(p_yh, p_wouth, out, 4096, 1024);
}